// round 1
// baseline (speedup 1.0000x reference)
#include <cuda_runtime.h>

// ----------------------------------------------------------------------------
// Fusion_12867722019048 — trimodal fusion head, fully fused per-row kernel.
//
// Algebraic simplification: all maxpool2 inputs are positive (sigmoid outputs
// and their products), so the pools factor:
//   fusion F[ix*32 + iy*8 + iz] = mx[ix] * m2y[iy] * mz[iz]
// with mx = pairwise max of x_h (8), m2y = max-of-4 of y_h (4),
// mz = pairwise max of z_h (8).
// ----------------------------------------------------------------------------

__device__ __forceinline__ float sigmoidf_(float x) {
    return __fdividef(1.0f, 1.0f + __expf(-x));
}
__device__ __forceinline__ float gatef_(float x, float rm) {
    return x * sigmoidf_(fabsf(x - rm));
}
__device__ __forceinline__ float leakyf_(float x) {
    return x > 0.0f ? x : 0.01f * x;
}

// 16x64 matvec + sigmoid: h = sigmoid(W @ x + b), W row-major [16,64]
__device__ __forceinline__ void matvec16_sig(
    const float* __restrict__ x, const float* __restrict__ W,
    const float* __restrict__ b, float h[16])
{
    float acc[16];
#pragma unroll
    for (int j = 0; j < 16; j++) acc[j] = __ldg(b + j);
#pragma unroll 4
    for (int k = 0; k < 64; k += 4) {
        float4 xv = *reinterpret_cast<const float4*>(x + k);
#pragma unroll
        for (int j = 0; j < 16; j++) {
            float4 w = __ldg(reinterpret_cast<const float4*>(W + j * 64 + k));
            acc[j] = fmaf(xv.x, w.x, acc[j]);
            acc[j] = fmaf(xv.y, w.y, acc[j]);
            acc[j] = fmaf(xv.z, w.z, acc[j]);
            acc[j] = fmaf(xv.w, w.w, acc[j]);
        }
    }
#pragma unroll
    for (int j = 0; j < 16; j++) h[j] = sigmoidf_(acc[j]);
}

// Build pooled fusion factors: P[32] = mx (x) m2y, mz[8]
__device__ __forceinline__ void build_PF(
    const float* __restrict__ xr, const float* __restrict__ yr,
    const float* __restrict__ zr,
    const float* __restrict__ Wx, const float* __restrict__ bx,
    const float* __restrict__ Wy, const float* __restrict__ by,
    const float* __restrict__ Wz, const float* __restrict__ bz,
    float P[32], float mz[8])
{
    float h[16];
    matvec16_sig(xr, Wx, bx, h);
    float mx[8];
#pragma unroll
    for (int i = 0; i < 8; i++) mx[i] = fmaxf(h[2 * i], h[2 * i + 1]);

    matvec16_sig(yr, Wy, by, h);
    float m2y[4];
#pragma unroll
    for (int i = 0; i < 4; i++)
        m2y[i] = fmaxf(fmaxf(h[4 * i], h[4 * i + 1]),
                       fmaxf(h[4 * i + 2], h[4 * i + 3]));

    matvec16_sig(zr, Wz, bz, h);
#pragma unroll
    for (int i = 0; i < 8; i++) mz[i] = fmaxf(h[2 * i], h[2 * i + 1]);

#pragma unroll
    for (int ix = 0; ix < 8; ix++)
#pragma unroll
        for (int iy = 0; iy < 4; iy++) P[ix * 4 + iy] = mx[ix] * m2y[iy];
}

// dot(Wrow[256], F) where F[u*8+t] = P[u]*mz[t]
__device__ __forceinline__ float fuse_dot(
    const float* __restrict__ Wrow, const float P[32], const float mz[8])
{
    float s0 = 0.0f, s1 = 0.0f;
#pragma unroll
    for (int u = 0; u < 32; u += 2) {
        float4 a0 = __ldg(reinterpret_cast<const float4*>(Wrow + u * 8));
        float4 a1 = __ldg(reinterpret_cast<const float4*>(Wrow + u * 8 + 4));
        float4 b0 = __ldg(reinterpret_cast<const float4*>(Wrow + u * 8 + 8));
        float4 b1 = __ldg(reinterpret_cast<const float4*>(Wrow + u * 8 + 12));
        float t0 = a0.x * mz[0];
        t0 = fmaf(a0.y, mz[1], t0);
        t0 = fmaf(a0.z, mz[2], t0);
        t0 = fmaf(a0.w, mz[3], t0);
        t0 = fmaf(a1.x, mz[4], t0);
        t0 = fmaf(a1.y, mz[5], t0);
        t0 = fmaf(a1.z, mz[6], t0);
        t0 = fmaf(a1.w, mz[7], t0);
        float t1 = b0.x * mz[0];
        t1 = fmaf(b0.y, mz[1], t1);
        t1 = fmaf(b0.z, mz[2], t1);
        t1 = fmaf(b0.w, mz[3], t1);
        t1 = fmaf(b1.x, mz[4], t1);
        t1 = fmaf(b1.y, mz[5], t1);
        t1 = fmaf(b1.z, mz[6], t1);
        t1 = fmaf(b1.w, mz[7], t1);
        s0 = fmaf(P[u], t0, s0);
        s1 = fmaf(P[u + 1], t1, s1);
    }
    return s0 + s1;
}

__global__ void __launch_bounds__(256, 1) fusion_kernel(
    const float* __restrict__ a, const float* __restrict__ v,
    const float* __restrict__ l, const float* __restrict__ pa,
    const float* __restrict__ pv, const float* __restrict__ pl,
    const float* __restrict__ mean,
    const float* __restrict__ Wa, const float* __restrict__ ba,
    const float* __restrict__ Wv, const float* __restrict__ bv,
    const float* __restrict__ Wl, const float* __restrict__ bl,
    const float* __restrict__ Wap, const float* __restrict__ bap,
    const float* __restrict__ Wvp, const float* __restrict__ bvp,
    const float* __restrict__ Wlp, const float* __restrict__ blp,
    const float* __restrict__ Wf1, const float* __restrict__ bf1,
    const float* __restrict__ Wfp1, const float* __restrict__ bfp1,
    const float* __restrict__ Wng, const float* __restrict__ bng,
    const float* __restrict__ rm1, const float* __restrict__ rm2,
    float* __restrict__ out, int nrows)
{
    // Wng transposed into smem: sWngT[k*64 + o] = Wng[o*128 + k]
    __shared__ float sWngT[128 * 64];
    for (int idx = threadIdx.x; idx < 128 * 64; idx += blockDim.x) {
        int k = idx >> 6, o = idx & 63;
        sWngT[idx] = Wng[o * 128 + k];
    }
    __syncthreads();

    for (int row = blockIdx.x * blockDim.x + threadIdx.x; row < nrows;
         row += gridDim.x * blockDim.x) {
        const int off = row * 64;

        // ---- fusion_2 pooled factors first (keeps reg pressure low) ----
        float P[32], mz[8];
        build_PF(pa + off, pv + off, pl + off,
                 Wap, bap, Wvp, bvp, Wlp, blp, P, mz);

        // ---- accumulate out64 = ng1 @ Wng^T + bng via rank-1 updates ----
        float acc[64];
#pragma unroll
        for (int o = 0; o < 64; o++) acc[o] = __ldg(bng + o);

        // mean contribution (cols 64..127 of Wng)
#pragma unroll 1
        for (int k = 0; k < 64; k++) {
            float g = gatef_(__ldg(mean + off + k), __ldg(rm1 + 64 + k));
            const float* c = sWngT + (64 + k) * 64;
#pragma unroll
            for (int o = 0; o < 64; o += 4) {
                float4 w = *reinterpret_cast<const float4*>(c + o);
                acc[o + 0] = fmaf(g, w.x, acc[o + 0]);
                acc[o + 1] = fmaf(g, w.y, acc[o + 1]);
                acc[o + 2] = fmaf(g, w.z, acc[o + 2]);
                acc[o + 3] = fmaf(g, w.w, acc[o + 3]);
            }
        }

        // fusion_2 contribution (cols 0..63 of Wng)
#pragma unroll 1
        for (int o2 = 0; o2 < 64; o2++) {
            float raw = __ldg(bfp1 + o2) + fuse_dot(Wfp1 + o2 * 256, P, mz);
            float g = gatef_(leakyf_(raw), __ldg(rm1 + o2));
            const float* c = sWngT + o2 * 64;
#pragma unroll
            for (int o = 0; o < 64; o += 4) {
                float4 w = *reinterpret_cast<const float4*>(c + o);
                acc[o + 0] = fmaf(g, w.x, acc[o + 0]);
                acc[o + 1] = fmaf(g, w.y, acc[o + 1]);
                acc[o + 2] = fmaf(g, w.z, acc[o + 2]);
                acc[o + 3] = fmaf(g, w.w, acc[o + 3]);
            }
        }

        float* orow = out + row * 128;
#pragma unroll
        for (int o = 0; o < 64; o++)
            orow[o] = gatef_(acc[o], __ldg(rm2 + o));

        // ---- fusion_1 directly gated into output cols 64..127 ----
        build_PF(a + off, v + off, l + off,
                 Wa, ba, Wv, bv, Wl, bl, P, mz);
#pragma unroll 1
        for (int o = 0; o < 64; o++) {
            float raw = __ldg(bf1 + o) + fuse_dot(Wf1 + o * 256, P, mz);
            orow[64 + o] = gatef_(leakyf_(raw), __ldg(rm2 + 64 + o));
        }
    }
}

extern "C" void kernel_launch(void* const* d_in, const int* in_sizes, int n_in,
                              void* d_out, int out_size) {
    const float* a    = (const float*)d_in[0];
    const float* v    = (const float*)d_in[1];
    const float* l    = (const float*)d_in[2];
    const float* pa   = (const float*)d_in[3];
    const float* pv   = (const float*)d_in[4];
    const float* pl   = (const float*)d_in[5];
    const float* mean = (const float*)d_in[6];
    const float* Wa   = (const float*)d_in[7];
    const float* ba   = (const float*)d_in[8];
    const float* Wv   = (const float*)d_in[9];
    const float* bv   = (const float*)d_in[10];
    const float* Wl   = (const float*)d_in[11];
    const float* bl   = (const float*)d_in[12];
    const float* Wap  = (const float*)d_in[13];
    const float* bap  = (const float*)d_in[14];
    const float* Wvp  = (const float*)d_in[15];
    const float* bvp  = (const float*)d_in[16];
    const float* Wlp  = (const float*)d_in[17];
    const float* blp  = (const float*)d_in[18];
    const float* Wf1  = (const float*)d_in[19];
    const float* bf1  = (const float*)d_in[20];
    const float* Wfp1 = (const float*)d_in[21];
    const float* bfp1 = (const float*)d_in[22];
    const float* Wng  = (const float*)d_in[23];
    const float* bng  = (const float*)d_in[24];
    const float* rm1  = (const float*)d_in[25];
    const float* rm2  = (const float*)d_in[26];

    int nrows = in_sizes[0] / 64;

    fusion_kernel<<<296, 256>>>(
        a, v, l, pa, pv, pl, mean,
        Wa, ba, Wv, bv, Wl, bl,
        Wap, bap, Wvp, bvp, Wlp, blp,
        Wf1, bf1, Wfp1, bfp1, Wng, bng, rm1, rm2,
        (float*)d_out, nrows);
}

// round 2
// speedup vs baseline: 1.0039x; 1.0039x over previous
#include <cuda_runtime.h>

// ----------------------------------------------------------------------------
// Fusion_12867722019048 — trimodal fusion head, fully fused per-row kernel.
//
// Algebraic simplification: all maxpool2 inputs are positive (sigmoid outputs
// and their products), so the pools factor:
//   fusion F[ix*32 + iy*8 + iz] = mx[ix] * m2y[iy] * mz[iz]
// with mx = pairwise max of x_h (8), m2y = max-of-4 of y_h (4),
// mz = pairwise max of z_h (8).
// ----------------------------------------------------------------------------

__device__ __forceinline__ float sigmoidf_(float x) {
    return __fdividef(1.0f, 1.0f + __expf(-x));
}
__device__ __forceinline__ float gatef_(float x, float rm) {
    return x * sigmoidf_(fabsf(x - rm));
}
__device__ __forceinline__ float leakyf_(float x) {
    return x > 0.0f ? x : 0.01f * x;
}

// 16x64 matvec + sigmoid: h = sigmoid(W @ x + b), W row-major [16,64]
__device__ __forceinline__ void matvec16_sig(
    const float* __restrict__ x, const float* __restrict__ W,
    const float* __restrict__ b, float h[16])
{
    float acc[16];
#pragma unroll
    for (int j = 0; j < 16; j++) acc[j] = __ldg(b + j);
#pragma unroll 4
    for (int k = 0; k < 64; k += 4) {
        float4 xv = *reinterpret_cast<const float4*>(x + k);
#pragma unroll
        for (int j = 0; j < 16; j++) {
            float4 w = __ldg(reinterpret_cast<const float4*>(W + j * 64 + k));
            acc[j] = fmaf(xv.x, w.x, acc[j]);
            acc[j] = fmaf(xv.y, w.y, acc[j]);
            acc[j] = fmaf(xv.z, w.z, acc[j]);
            acc[j] = fmaf(xv.w, w.w, acc[j]);
        }
    }
#pragma unroll
    for (int j = 0; j < 16; j++) h[j] = sigmoidf_(acc[j]);
}

// Build pooled fusion factors: P[32] = mx (x) m2y, mz[8]
__device__ __forceinline__ void build_PF(
    const float* __restrict__ xr, const float* __restrict__ yr,
    const float* __restrict__ zr,
    const float* __restrict__ Wx, const float* __restrict__ bx,
    const float* __restrict__ Wy, const float* __restrict__ by,
    const float* __restrict__ Wz, const float* __restrict__ bz,
    float P[32], float mz[8])
{
    float h[16];
    matvec16_sig(xr, Wx, bx, h);
    float mx[8];
#pragma unroll
    for (int i = 0; i < 8; i++) mx[i] = fmaxf(h[2 * i], h[2 * i + 1]);

    matvec16_sig(yr, Wy, by, h);
    float m2y[4];
#pragma unroll
    for (int i = 0; i < 4; i++)
        m2y[i] = fmaxf(fmaxf(h[4 * i], h[4 * i + 1]),
                       fmaxf(h[4 * i + 2], h[4 * i + 3]));

    matvec16_sig(zr, Wz, bz, h);
#pragma unroll
    for (int i = 0; i < 8; i++) mz[i] = fmaxf(h[2 * i], h[2 * i + 1]);

#pragma unroll
    for (int ix = 0; ix < 8; ix++)
#pragma unroll
        for (int iy = 0; iy < 4; iy++) P[ix * 4 + iy] = mx[ix] * m2y[iy];
}

// dot(Wrow[256], F) where F[u*8+t] = P[u]*mz[t]
__device__ __forceinline__ float fuse_dot(
    const float* __restrict__ Wrow, const float P[32], const float mz[8])
{
    float s0 = 0.0f, s1 = 0.0f;
#pragma unroll
    for (int u = 0; u < 32; u += 2) {
        float4 a0 = __ldg(reinterpret_cast<const float4*>(Wrow + u * 8));
        float4 a1 = __ldg(reinterpret_cast<const float4*>(Wrow + u * 8 + 4));
        float4 b0 = __ldg(reinterpret_cast<const float4*>(Wrow + u * 8 + 8));
        float4 b1 = __ldg(reinterpret_cast<const float4*>(Wrow + u * 8 + 12));
        float t0 = a0.x * mz[0];
        t0 = fmaf(a0.y, mz[1], t0);
        t0 = fmaf(a0.z, mz[2], t0);
        t0 = fmaf(a0.w, mz[3], t0);
        t0 = fmaf(a1.x, mz[4], t0);
        t0 = fmaf(a1.y, mz[5], t0);
        t0 = fmaf(a1.z, mz[6], t0);
        t0 = fmaf(a1.w, mz[7], t0);
        float t1 = b0.x * mz[0];
        t1 = fmaf(b0.y, mz[1], t1);
        t1 = fmaf(b0.z, mz[2], t1);
        t1 = fmaf(b0.w, mz[3], t1);
        t1 = fmaf(b1.x, mz[4], t1);
        t1 = fmaf(b1.y, mz[5], t1);
        t1 = fmaf(b1.z, mz[6], t1);
        t1 = fmaf(b1.w, mz[7], t1);
        s0 = fmaf(P[u], t0, s0);
        s1 = fmaf(P[u + 1], t1, s1);
    }
    return s0 + s1;
}

__global__ void __launch_bounds__(256, 1) fusion_kernel(
    const float* __restrict__ a, const float* __restrict__ v,
    const float* __restrict__ l, const float* __restrict__ pa,
    const float* __restrict__ pv, const float* __restrict__ pl,
    const float* __restrict__ mean,
    const float* __restrict__ Wa, const float* __restrict__ ba,
    const float* __restrict__ Wv, const float* __restrict__ bv,
    const float* __restrict__ Wl, const float* __restrict__ bl,
    const float* __restrict__ Wap, const float* __restrict__ bap,
    const float* __restrict__ Wvp, const float* __restrict__ bvp,
    const float* __restrict__ Wlp, const float* __restrict__ blp,
    const float* __restrict__ Wf1, const float* __restrict__ bf1,
    const float* __restrict__ Wfp1, const float* __restrict__ bfp1,
    const float* __restrict__ Wng, const float* __restrict__ bng,
    const float* __restrict__ rm1, const float* __restrict__ rm2,
    float* __restrict__ out, int nrows)
{
    // Wng transposed into smem: sWngT[k*64 + o] = Wng[o*128 + k]
    __shared__ float sWngT[128 * 64];
    for (int idx = threadIdx.x; idx < 128 * 64; idx += blockDim.x) {
        int k = idx >> 6, o = idx & 63;
        sWngT[idx] = Wng[o * 128 + k];
    }
    __syncthreads();

    for (int row = blockIdx.x * blockDim.x + threadIdx.x; row < nrows;
         row += gridDim.x * blockDim.x) {
        const int off = row * 64;

        // ---- fusion_2 pooled factors first (keeps reg pressure low) ----
        float P[32], mz[8];
        build_PF(pa + off, pv + off, pl + off,
                 Wap, bap, Wvp, bvp, Wlp, blp, P, mz);

        // ---- accumulate out64 = ng1 @ Wng^T + bng via rank-1 updates ----
        float acc[64];
#pragma unroll
        for (int o = 0; o < 64; o++) acc[o] = __ldg(bng + o);

        // mean contribution (cols 64..127 of Wng)
#pragma unroll 1
        for (int k = 0; k < 64; k++) {
            float g = gatef_(__ldg(mean + off + k), __ldg(rm1 + 64 + k));
            const float* c = sWngT + (64 + k) * 64;
#pragma unroll
            for (int o = 0; o < 64; o += 4) {
                float4 w = *reinterpret_cast<const float4*>(c + o);
                acc[o + 0] = fmaf(g, w.x, acc[o + 0]);
                acc[o + 1] = fmaf(g, w.y, acc[o + 1]);
                acc[o + 2] = fmaf(g, w.z, acc[o + 2]);
                acc[o + 3] = fmaf(g, w.w, acc[o + 3]);
            }
        }

        // fusion_2 contribution (cols 0..63 of Wng)
#pragma unroll 1
        for (int o2 = 0; o2 < 64; o2++) {
            float raw = __ldg(bfp1 + o2) + fuse_dot(Wfp1 + o2 * 256, P, mz);
            float g = gatef_(leakyf_(raw), __ldg(rm1 + o2));
            const float* c = sWngT + o2 * 64;
#pragma unroll
            for (int o = 0; o < 64; o += 4) {
                float4 w = *reinterpret_cast<const float4*>(c + o);
                acc[o + 0] = fmaf(g, w.x, acc[o + 0]);
                acc[o + 1] = fmaf(g, w.y, acc[o + 1]);
                acc[o + 2] = fmaf(g, w.z, acc[o + 2]);
                acc[o + 3] = fmaf(g, w.w, acc[o + 3]);
            }
        }

        float* orow = out + row * 128;
#pragma unroll
        for (int o = 0; o < 64; o++)
            orow[o] = gatef_(acc[o], __ldg(rm2 + o));

        // ---- fusion_1 directly gated into output cols 64..127 ----
        build_PF(a + off, v + off, l + off,
                 Wa, ba, Wv, bv, Wl, bl, P, mz);
#pragma unroll 1
        for (int o = 0; o < 64; o++) {
            float raw = __ldg(bf1 + o) + fuse_dot(Wf1 + o * 256, P, mz);
            orow[64 + o] = gatef_(leakyf_(raw), __ldg(rm2 + 64 + o));
        }
    }
}

extern "C" void kernel_launch(void* const* d_in, const int* in_sizes, int n_in,
                              void* d_out, int out_size) {
    const float* a    = (const float*)d_in[0];
    const float* v    = (const float*)d_in[1];
    const float* l    = (const float*)d_in[2];
    const float* pa   = (const float*)d_in[3];
    const float* pv   = (const float*)d_in[4];
    const float* pl   = (const float*)d_in[5];
    const float* mean = (const float*)d_in[6];
    const float* Wa   = (const float*)d_in[7];
    const float* ba   = (const float*)d_in[8];
    const float* Wv   = (const float*)d_in[9];
    const float* bv   = (const float*)d_in[10];
    const float* Wl   = (const float*)d_in[11];
    const float* bl   = (const float*)d_in[12];
    const float* Wap  = (const float*)d_in[13];
    const float* bap  = (const float*)d_in[14];
    const float* Wvp  = (const float*)d_in[15];
    const float* bvp  = (const float*)d_in[16];
    const float* Wlp  = (const float*)d_in[17];
    const float* blp  = (const float*)d_in[18];
    const float* Wf1  = (const float*)d_in[19];
    const float* bf1  = (const float*)d_in[20];
    const float* Wfp1 = (const float*)d_in[21];
    const float* bfp1 = (const float*)d_in[22];
    const float* Wng  = (const float*)d_in[23];
    const float* bng  = (const float*)d_in[24];
    const float* rm1  = (const float*)d_in[25];
    const float* rm2  = (const float*)d_in[26];

    int nrows = in_sizes[0] / 64;

    fusion_kernel<<<296, 256>>>(
        a, v, l, pa, pv, pl, mean,
        Wa, ba, Wv, bv, Wl, bl,
        Wap, bap, Wvp, bvp, Wlp, blp,
        Wf1, bf1, Wfp1, bfp1, Wng, bng, rm1, rm2,
        (float*)d_out, nrows);
}

// round 3
// speedup vs baseline: 1.3137x; 1.3086x over previous
#include <cuda_runtime.h>

typedef unsigned long long ull;

// Transposed weights, produced by setup kernel each replay.
__device__ float g_WT[2][256 * 64];  // [k][c] for Wfp1 (0) and Wf1 (1)
__device__ float g_WngT[128 * 64];   // [k][o]

__global__ void setup_kernel(const float* __restrict__ Wfp1,
                             const float* __restrict__ Wf1,
                             const float* __restrict__ Wng) {
    int tid = blockIdx.x * blockDim.x + threadIdx.x;
    int stride = gridDim.x * blockDim.x;
    for (int i = tid; i < 256 * 64; i += stride) {
        int k = i >> 6, c = i & 63;
        g_WT[0][i] = Wfp1[c * 256 + k];
        g_WT[1][i] = Wf1[c * 256 + k];
    }
    for (int i = tid; i < 128 * 64; i += stride) {
        int k = i >> 6, c = i & 63;
        g_WngT[i] = Wng[c * 128 + k];
    }
}

__device__ __forceinline__ float sigmoidf_(float x) {
    return __fdividef(1.0f, 1.0f + __expf(-x));
}
__device__ __forceinline__ float gatef_(float x, float rm) {
    return x * sigmoidf_(fabsf(x - rm));
}
__device__ __forceinline__ float leakyf_(float x) {
    return x > 0.0f ? x : 0.01f * x;
}
__device__ __forceinline__ ull dup2_(float x) {
    ull r; unsigned u = __float_as_uint(x);
    asm("mov.b64 %0, {%1, %1};" : "=l"(r) : "r"(u));
    return r;
}
__device__ __forceinline__ void ffma2_(ull& d, ull a, ull b) {
    asm("fma.rn.f32x2 %0, %1, %2, %0;" : "+l"(d) : "l"(a), "l"(b));
}
__device__ __forceinline__ float2 unpk_(ull v) {
    float2 r;
    asm("mov.b64 {%0, %1}, %2;" : "=f"(r.x), "=f"(r.y) : "l"(v));
    return r;
}

// 4x4 register-tile GEMM: acc[i][j] holds cols (c0+2j, c0+2j+1) of row r0+i.
// pF = F + r0 (layout [K][64]); pW = WT + c0 (layout [K][64]).
template <int K>
__device__ __forceinline__ void gemm_tile(const float* __restrict__ pF,
                                          const float* __restrict__ pW,
                                          ull acc[4][2]) {
#pragma unroll 8
    for (int k = 0; k < K; k++) {
        float4 f = *reinterpret_cast<const float4*>(pF + k * 64);
        ulonglong2 w = *reinterpret_cast<const ulonglong2*>(pW + k * 64);
        ull d0 = dup2_(f.x), d1 = dup2_(f.y), d2 = dup2_(f.z), d3 = dup2_(f.w);
        ffma2_(acc[0][0], d0, w.x); ffma2_(acc[0][1], d0, w.y);
        ffma2_(acc[1][0], d1, w.x); ffma2_(acc[1][1], d1, w.y);
        ffma2_(acc[2][0], d2, w.x); ffma2_(acc[2][1], d2, w.y);
        ffma2_(acc[3][0], d3, w.x); ffma2_(acc[3][1], d3, w.y);
    }
}

// Matvecs + sigmoid + pooling for one fusion branch.
// Thread (r, q): outputs j = 4q..4q+3 of all 3 modalities for row r.
// Writes m2y (pm[q]) and mz pair (pm[4+2q], pm[5+2q]); keeps mx pair in regs.
__device__ __forceinline__ void stage_factors(
    const float* __restrict__ sIn, float* __restrict__ sPmz,
    const float* __restrict__ Wx, const float* __restrict__ bx,
    const float* __restrict__ Wy, const float* __restrict__ by,
    const float* __restrict__ Wz, const float* __restrict__ bz,
    int r, int q, float& mx0, float& mx1) {
    float a0[4], a1[4], a2[4];
#pragma unroll
    for (int jj = 0; jj < 4; jj++) {
        a0[jj] = __ldg(bx + q * 4 + jj);
        a1[jj] = __ldg(by + q * 4 + jj);
        a2[jj] = __ldg(bz + q * 4 + jj);
    }
    const float* xr = sIn + r * 68;
#pragma unroll 4
    for (int k = 0; k < 64; k += 4) {
        float4 x0 = *reinterpret_cast<const float4*>(xr + k);
        float4 x1 = *reinterpret_cast<const float4*>(xr + 4352 + k);
        float4 x2 = *reinterpret_cast<const float4*>(xr + 8704 + k);
#pragma unroll
        for (int jj = 0; jj < 4; jj++) {
            int woff = (q * 4 + jj) * 64 + k;
            float4 w0 = __ldg(reinterpret_cast<const float4*>(Wx + woff));
            a0[jj] = fmaf(x0.x, w0.x, a0[jj]); a0[jj] = fmaf(x0.y, w0.y, a0[jj]);
            a0[jj] = fmaf(x0.z, w0.z, a0[jj]); a0[jj] = fmaf(x0.w, w0.w, a0[jj]);
            float4 w1 = __ldg(reinterpret_cast<const float4*>(Wy + woff));
            a1[jj] = fmaf(x1.x, w1.x, a1[jj]); a1[jj] = fmaf(x1.y, w1.y, a1[jj]);
            a1[jj] = fmaf(x1.z, w1.z, a1[jj]); a1[jj] = fmaf(x1.w, w1.w, a1[jj]);
            float4 w2 = __ldg(reinterpret_cast<const float4*>(Wz + woff));
            a2[jj] = fmaf(x2.x, w2.x, a2[jj]); a2[jj] = fmaf(x2.y, w2.y, a2[jj]);
            a2[jj] = fmaf(x2.z, w2.z, a2[jj]); a2[jj] = fmaf(x2.w, w2.w, a2[jj]);
        }
    }
    float hx[4], hy[4], hz[4];
#pragma unroll
    for (int jj = 0; jj < 4; jj++) {
        hx[jj] = sigmoidf_(a0[jj]);
        hy[jj] = sigmoidf_(a1[jj]);
        hz[jj] = sigmoidf_(a2[jj]);
    }
    mx0 = fmaxf(hx[0], hx[1]);
    mx1 = fmaxf(hx[2], hx[3]);
    float* pm = sPmz + r * 16;
    pm[q] = fmaxf(fmaxf(hy[0], hy[1]), fmaxf(hy[2], hy[3]));
    pm[4 + 2 * q] = fmaxf(hz[0], hz[1]);
    pm[5 + 2 * q] = fmaxf(hz[2], hz[3]);
}

// Expand F (layout [256][64]) for k in [64q, 64q+64) of row r.
__device__ __forceinline__ void expand_F(const float* __restrict__ sPmz,
                                         float* __restrict__ sF, int r, int q,
                                         float mx0, float mx1) {
    const float* pm = sPmz + r * 16;
    float m2y[4], mz[8];
#pragma unroll
    for (int i = 0; i < 4; i++) m2y[i] = pm[i];
#pragma unroll
    for (int i = 0; i < 8; i++) mz[i] = pm[4 + i];
#pragma unroll
    for (int uu = 0; uu < 8; uu++) {
        float Pu = (uu < 4 ? mx0 : mx1) * m2y[uu & 3];
        float* dst = sF + (q * 64 + uu * 8) * 64 + r;
#pragma unroll
        for (int t = 0; t < 8; t++) dst[t * 64] = Pu * mz[t];
    }
}

// Shared layout (floats):
//  sA   @ 0      : 16384  (sIn 3x64x68 | F expand 256x64 | sGT2 64x65)
//  sW   @ 16384  : 16384  (fusion weight tile, transposed)
//  sGT  @ 32768  : 8192   (gated concat, [128][64])
//  sWng @ 40960  : 8192   (WngT)
//  sMean@ 49152  : 4352   (64x68)
//  sPmz @ 53504  : 1024   (64x16)
#define SMEM_FLOATS 54528

__global__ void __launch_bounds__(256) fusion_main(
    const float* __restrict__ a, const float* __restrict__ v,
    const float* __restrict__ l, const float* __restrict__ pa,
    const float* __restrict__ pv, const float* __restrict__ pl,
    const float* __restrict__ mean,
    const float* __restrict__ Wa, const float* __restrict__ ba,
    const float* __restrict__ Wv, const float* __restrict__ bv,
    const float* __restrict__ Wl, const float* __restrict__ bl,
    const float* __restrict__ Wap, const float* __restrict__ bap,
    const float* __restrict__ Wvp, const float* __restrict__ bvp,
    const float* __restrict__ Wlp, const float* __restrict__ blp,
    const float* __restrict__ bf1, const float* __restrict__ bfp1,
    const float* __restrict__ bng, const float* __restrict__ rm1,
    const float* __restrict__ rm2, float* __restrict__ out) {
    extern __shared__ __align__(16) float smem[];
    float* sA = smem;
    float* sW = smem + 16384;
    float* sGT = smem + 32768;
    float* sWng = smem + 40960;
    float* sMean = smem + 49152;
    float* sPmz = smem + 53504;

    const int tid = threadIdx.x;
    const int row0 = blockIdx.x * 64;
    const int r = tid >> 2, q = tid & 3;
    const int r0 = (tid >> 4) * 4;
    const int c0 = (tid & 15) * 4;

    // ---- P0: stage pa/pv/pl -> sA(sIn), mean -> sMean, Wfp1T -> sW ----
    {
        const float* srcs[3] = {pa + row0 * 64, pv + row0 * 64, pl + row0 * 64};
#pragma unroll
        for (int m = 0; m < 3; m++) {
            const float4* s = reinterpret_cast<const float4*>(srcs[m]);
#pragma unroll
            for (int it = 0; it < 4; it++) {
                int i = tid + it * 256;
                *reinterpret_cast<float4*>(sA + m * 4352 + (i >> 4) * 68 +
                                           (i & 15) * 4) = s[i];
            }
        }
        const float4* ms = reinterpret_cast<const float4*>(mean + row0 * 64);
#pragma unroll
        for (int it = 0; it < 4; it++) {
            int i = tid + it * 256;
            *reinterpret_cast<float4*>(sMean + (i >> 4) * 68 + (i & 15) * 4) = ms[i];
        }
        const float4* gw = reinterpret_cast<const float4*>(g_WT[0]);
        float4* dw = reinterpret_cast<float4*>(sW);
#pragma unroll
        for (int it = 0; it < 16; it++) dw[tid + it * 256] = gw[tid + it * 256];
    }
    __syncthreads();

    // ---- P1: fusion-2 matvecs + pooling ----
    float mx0, mx1;
    stage_factors(sA, sPmz, Wap, bap, Wvp, bvp, Wlp, blp, r, q, mx0, mx1);
    __syncthreads();

    // ---- P2: expand F2 over sA ----
    expand_F(sPmz, sA, r, q, mx0, mx1);
    __syncthreads();

    // ---- P3: GEMM1 ----
    ull acc[4][2] = {};
    gemm_tile<256>(sA + r0, sW + c0, acc);
    __syncthreads();
    // write raw results to sGT2 (= sA region, stride 65)
#pragma unroll
    for (int i = 0; i < 4; i++)
#pragma unroll
        for (int j = 0; j < 2; j++) {
            float2 p = unpk_(acc[i][j]);
            sA[(r0 + i) * 65 + c0 + 2 * j] = p.x;
            sA[(r0 + i) * 65 + c0 + 2 * j + 1] = p.y;
        }
    __syncthreads();

    // ---- P4: gate into sGT [128][64]; load Wf1T -> sW, WngT -> sWng ----
#pragma unroll
    for (int it = 0; it < 32; it++) {
        int i = tid + it * 256;
        int k = i >> 6, rr = i & 63;
        float val;
        if (k < 64)
            val = gatef_(leakyf_(sA[rr * 65 + k] + __ldg(bfp1 + k)), __ldg(rm1 + k));
        else
            val = gatef_(sMean[rr * 68 + (k - 64)], __ldg(rm1 + k));
        sGT[k * 64 + rr] = val;
    }
    {
        const float4* gw = reinterpret_cast<const float4*>(g_WT[1]);
        float4* dw = reinterpret_cast<float4*>(sW);
#pragma unroll
        for (int it = 0; it < 16; it++) dw[tid + it * 256] = gw[tid + it * 256];
        const float4* gn = reinterpret_cast<const float4*>(g_WngT);
        float4* dn = reinterpret_cast<float4*>(sWng);
#pragma unroll
        for (int it = 0; it < 8; it++) dn[tid + it * 256] = gn[tid + it * 256];
    }
    __syncthreads();

    // ---- P5: stage a/v/l -> sA; GEMM2 -> out[:,0:64] ----
    {
        const float* srcs[3] = {a + row0 * 64, v + row0 * 64, l + row0 * 64};
#pragma unroll
        for (int m = 0; m < 3; m++) {
            const float4* s = reinterpret_cast<const float4*>(srcs[m]);
#pragma unroll
            for (int it = 0; it < 4; it++) {
                int i = tid + it * 256;
                *reinterpret_cast<float4*>(sA + m * 4352 + (i >> 4) * 68 +
                                           (i & 15) * 4) = s[i];
            }
        }
        ull acc2[4][2] = {};
        gemm_tile<128>(sGT + r0, sWng + c0, acc2);
        float4 bb = __ldg(reinterpret_cast<const float4*>(bng + c0));
        float4 rr2 = __ldg(reinterpret_cast<const float4*>(rm2 + c0));
        float bbv[4] = {bb.x, bb.y, bb.z, bb.w};
        float rmv[4] = {rr2.x, rr2.y, rr2.z, rr2.w};
#pragma unroll
        for (int i = 0; i < 4; i++) {
            float og[4];
#pragma unroll
            for (int j = 0; j < 2; j++) {
                float2 p = unpk_(acc2[i][j]);
                og[2 * j] = gatef_(p.x + bbv[2 * j], rmv[2 * j]);
                og[2 * j + 1] = gatef_(p.y + bbv[2 * j + 1], rmv[2 * j + 1]);
            }
            *reinterpret_cast<float4*>(out + (row0 + r0 + i) * 128 + c0) =
                make_float4(og[0], og[1], og[2], og[3]);
        }
    }
    __syncthreads();

    // ---- P6: fusion-1 matvecs + pooling ----
    stage_factors(sA, sPmz, Wa, ba, Wv, bv, Wl, bl, r, q, mx0, mx1);
    __syncthreads();

    // ---- P7: expand F1 over sA ----
    expand_F(sPmz, sA, r, q, mx0, mx1);
    __syncthreads();

    // ---- P8: GEMM3 -> out[:,64:128] ----
    {
        ull acc3[4][2] = {};
        gemm_tile<256>(sA + r0, sW + c0, acc3);
        float4 bb = __ldg(reinterpret_cast<const float4*>(bf1 + c0));
        float4 rr2 = __ldg(reinterpret_cast<const float4*>(rm2 + 64 + c0));
        float bbv[4] = {bb.x, bb.y, bb.z, bb.w};
        float rmv[4] = {rr2.x, rr2.y, rr2.z, rr2.w};
#pragma unroll
        for (int i = 0; i < 4; i++) {
            float og[4];
#pragma unroll
            for (int j = 0; j < 2; j++) {
                float2 p = unpk_(acc3[i][j]);
                og[2 * j] = gatef_(leakyf_(p.x + bbv[2 * j]), rmv[2 * j]);
                og[2 * j + 1] = gatef_(leakyf_(p.y + bbv[2 * j + 1]), rmv[2 * j + 1]);
            }
            *reinterpret_cast<float4*>(out + (row0 + r0 + i) * 128 + 64 + c0) =
                make_float4(og[0], og[1], og[2], og[3]);
        }
    }
}

extern "C" void kernel_launch(void* const* d_in, const int* in_sizes, int n_in,
                              void* d_out, int out_size) {
    const float* a    = (const float*)d_in[0];
    const float* v    = (const float*)d_in[1];
    const float* l    = (const float*)d_in[2];
    const float* pa   = (const float*)d_in[3];
    const float* pv   = (const float*)d_in[4];
    const float* pl   = (const float*)d_in[5];
    const float* mean = (const float*)d_in[6];
    const float* Wa   = (const float*)d_in[7];
    const float* ba   = (const float*)d_in[8];
    const float* Wv   = (const float*)d_in[9];
    const float* bv   = (const float*)d_in[10];
    const float* Wl   = (const float*)d_in[11];
    const float* bl   = (const float*)d_in[12];
    const float* Wap  = (const float*)d_in[13];
    const float* bap  = (const float*)d_in[14];
    const float* Wvp  = (const float*)d_in[15];
    const float* bvp  = (const float*)d_in[16];
    const float* Wlp  = (const float*)d_in[17];
    const float* blp  = (const float*)d_in[18];
    const float* Wf1  = (const float*)d_in[19];
    const float* bf1  = (const float*)d_in[20];
    const float* Wfp1 = (const float*)d_in[21];
    const float* bfp1 = (const float*)d_in[22];
    const float* Wng  = (const float*)d_in[23];
    const float* bng  = (const float*)d_in[24];
    const float* rm1  = (const float*)d_in[25];
    const float* rm2  = (const float*)d_in[26];

    int nrows = in_sizes[0] / 64;
    static int smem_set = 0;
    if (!smem_set) {
        cudaFuncSetAttribute(fusion_main,
                             cudaFuncAttributeMaxDynamicSharedMemorySize,
                             SMEM_FLOATS * 4);
        smem_set = 1;
    }

    setup_kernel<<<64, 256>>>(Wfp1, Wf1, Wng);
    fusion_main<<<nrows / 64, 256, SMEM_FLOATS * 4>>>(
        a, v, l, pa, pv, pl, mean,
        Wa, ba, Wv, bv, Wl, bl,
        Wap, bap, Wvp, bvp, Wlp, blp,
        bf1, bfp1, bng, rm1, rm2, (float*)d_out);
}